// round 4
// baseline (speedup 1.0000x reference)
#include <cuda_runtime.h>
#include <math.h>
#include <stdint.h>

// ---------------------------------------------------------------------------
// Problem constants
// ---------------------------------------------------------------------------
#define SRC   2048          // S
#define NB    10            // neighbors
#define DDIM  172           // D
#define EDIM  172           // EDGE
#define TDIM  100           // TD
#define EQ    272           // E  = D + TD
#define KD    444           // D + EDGE + TD
#define KDT   4440          // KD * N
#define HD    136           // head dim (E / H)

#define M0    (SRC*NB)      // 20480 rows prop0
#define M1    SRC           // 2048  rows prop1

// output layout offsets (float elements)
#define OUT_R0    0
#define OUT_R1    (SRC*NB*DDIM)
#define OUT_EDGE  (OUT_R1 + SRC*DDIM)
#define OUT_TD    (OUT_EDGE + SRC*NB*EDIM)

// ---------------------------------------------------------------------------
// Scratch (device globals; no allocation allowed)
// ---------------------------------------------------------------------------
__device__ float g_kvp0[M0 * 544];
__device__ float g_qp0 [M0 * EQ];
__device__ float g_o0  [M0 * EQ];
__device__ float g_a0  [M0 * EQ];
__device__ float g_h0  [M0 * DDIM];
__device__ float g_kvp1[M1 * 544];
__device__ float g_qp1 [M1 * EQ];
__device__ float g_o1  [M1 * EQ];
__device__ float g_a1  [M1 * EQ];
__device__ float g_h1  [M1 * DDIM];

// ---------------------------------------------------------------------------
// A/B gather functors (float4-aligned; all segment boundaries %4 == 0)
// ---------------------------------------------------------------------------
template<int MODE>
__device__ __forceinline__ float4 loadA(const float* __restrict__ A0,
                                        const float* __restrict__ A1,
                                        const float* __restrict__ A2,
                                        int lda, int row, int k)
{
    if (MODE == 0) {
        return *reinterpret_cast<const float4*>(A0 + (size_t)row * lda + k);
    } else if (MODE == 1) {
        int n2 = k / KD;
        int f  = k - n2 * KD;
        size_t sub = (size_t)row * NB + n2;
        if (f < DDIM)        return *reinterpret_cast<const float4*>(A0 + sub * DDIM + f);
        else if (f < 2*DDIM) return *reinterpret_cast<const float4*>(A1 + sub * EDIM + (f - DDIM));
        else                 return *reinterpret_cast<const float4*>(A2 + sub * TDIM + (f - 2*DDIM));
    } else if (MODE == 2) {
        if (k < DDIM) return *reinterpret_cast<const float4*>(A0 + (size_t)row * DDIM + k);
        else          return *reinterpret_cast<const float4*>(A1 + (size_t)row * TDIM + (k - DDIM));
    } else { // MODE == 3
        if (k < EQ)   return *reinterpret_cast<const float4*>(A0 + (size_t)row * EQ + k);
        else          return *reinterpret_cast<const float4*>(A1 + (size_t)row * DDIM + (k - EQ));
    }
}

template<int MODE>
__device__ __forceinline__ float4 loadB(const float* __restrict__ B0,
                                        const float* __restrict__ B1,
                                        int ldb, int n, int k)
{
    if (MODE == 0) {
        return *reinterpret_cast<const float4*>(B0 + (size_t)n * ldb + k);
    } else {
        if (n < EQ) return *reinterpret_cast<const float4*>(B0 + (size_t)n * KDT + k);
        else        return *reinterpret_cast<const float4*>(B1 + (size_t)(n - EQ) * KDT + k);
    }
}

// ---------------------------------------------------------------------------
// tf32 helpers
// ---------------------------------------------------------------------------
__device__ __forceinline__ uint32_t f2tf32(float f) {
    uint32_t u;
    asm("cvt.rna.tf32.f32 %0, %1;" : "=r"(u) : "f"(f));
    return u;
}

__device__ __forceinline__ void mma_tf32(float c[4], const uint32_t a[4],
                                         const uint32_t b[2]) {
    asm volatile(
        "mma.sync.aligned.m16n8k8.row.col.f32.tf32.tf32.f32 "
        "{%0,%1,%2,%3}, {%4,%5,%6,%7}, {%8,%9}, {%0,%1,%2,%3};"
        : "+f"(c[0]), "+f"(c[1]), "+f"(c[2]), "+f"(c[3])
        : "r"(a[0]), "r"(a[1]), "r"(a[2]), "r"(a[3]), "r"(b[0]), "r"(b[1]));
}

// ---------------------------------------------------------------------------
// mma.sync tf32 GEMM with swizzled fragment-native SMEM layout.
// CTA tile 128x64xBK32, 256 threads (8 warps, 4x2), warp tile 32x32.
//
// SMEM layout (per tile row of 32 floats, no padding):
//   element (row, k), k = s*8 + h*4 + t  (s:0..3, h:0..1, t:0..3)
//   stored at col = (s ^ (row&3))*8 + (t ^ 2*(row&1))*2 + h
// -> fragment pair (k=t, k=t+4) is an aligned uint2 (LDS.64), conflict-free
// -> staging writes 8-float chunks as two uint4 (STS.128), conflict-free
// SMEM total: 2*(128+64)*32*4 = 48 KB.
// ---------------------------------------------------------------------------
#define GM_SMEM ((2*128*32 + 2*64*32) * 4)   // 49152 bytes

template<int AMODE, int BMODE, bool RELU>
__global__ void __launch_bounds__(256)
gemm_mma(const float* __restrict__ A0, const float* __restrict__ A1,
         const float* __restrict__ A2, int lda,
         const float* __restrict__ B0, const float* __restrict__ B1, int ldb,
         const float* __restrict__ bias0, const float* __restrict__ bias1,
         float* __restrict__ C, int M, int N, int K, int ldc, float alpha)
{
    extern __shared__ uint32_t sh[];
    uint32_t* As = sh;                   // [2][128*32]
    uint32_t* Bs = sh + 2 * 128 * 32;    // [2][64*32]

    const int tid  = threadIdx.x;
    const int wid  = tid >> 5;
    const int lane = tid & 31;
    const int g    = lane >> 2;          // group 0..7
    const int t    = lane & 3;           // thread in group
    const int g3   = g & 3;
    const int tq   = ((t ^ ((g & 1) << 1)) << 1);   // swizzled t-column (floats)
    const int wm   = wid & 3;            // warp m position (0..3) x32 rows
    const int wn   = wid >> 2;           // warp n position (0..1) x32 cols
    const int m0   = blockIdx.y * 128;
    const int n0   = blockIdx.x * 64;

    float acc[2][4][4];
#pragma unroll
    for (int i = 0; i < 2; i++)
#pragma unroll
        for (int j = 0; j < 4; j++)
#pragma unroll
            for (int l = 0; l < 4; l++) acc[i][j][l] = 0.f;

    // staging decomposition: chunk = (row, s) covering k = s*8 .. s*8+7
    const int srow = tid >> 2;           // 0..63
    const int ss   = tid & 3;            // s
    const int KT   = (K + 31) >> 5;

    float4 raA[2][2];    // A chunks: rows srow, srow+64; [chunk][h]
    float4 raB[2];       // B chunk: row srow; [h]

#define FETCH(k0_)                                                             \
    do {                                                                       \
        const int gk = (k0_) + ss * 8;                                         \
        _Pragma("unroll")                                                      \
        for (int c = 0; c < 2; c++) {                                          \
            int r = srow + c * 64;                                             \
            raA[c][0] = (gk < K)                                               \
                      ? loadA<AMODE>(A0, A1, A2, lda, m0 + r, gk)              \
                      : make_float4(0.f, 0.f, 0.f, 0.f);                       \
            raA[c][1] = (gk + 4 < K)                                           \
                      ? loadA<AMODE>(A0, A1, A2, lda, m0 + r, gk + 4)          \
                      : make_float4(0.f, 0.f, 0.f, 0.f);                       \
        }                                                                      \
        int gn = n0 + srow;                                                    \
        raB[0] = (gn < N && gk < K)                                            \
               ? loadB<BMODE>(B0, B1, ldb, gn, gk)                             \
               : make_float4(0.f, 0.f, 0.f, 0.f);                              \
        raB[1] = (gn < N && gk + 4 < K)                                        \
               ? loadB<BMODE>(B0, B1, ldb, gn, gk + 4)                         \
               : make_float4(0.f, 0.f, 0.f, 0.f);                              \
    } while (0)

#define COMMIT(buf_)                                                           \
    do {                                                                       \
        uint32_t* Ab = As + (buf_) * 4096;                                     \
        uint32_t* Bb = Bs + (buf_) * 2048;                                     \
        _Pragma("unroll")                                                      \
        for (int c = 0; c < 2; c++) {                                          \
            int r = srow + c * 64;                                             \
            uint4 u0 = make_uint4(f2tf32(raA[c][0].x), f2tf32(raA[c][1].x),    \
                                  f2tf32(raA[c][0].y), f2tf32(raA[c][1].y));   \
            uint4 u1 = make_uint4(f2tf32(raA[c][0].z), f2tf32(raA[c][1].z),    \
                                  f2tf32(raA[c][0].w), f2tf32(raA[c][1].w));   \
            int base = r * 32 + ((ss ^ (r & 3)) << 3);                         \
            int o = (r & 1) << 2;                                              \
            *reinterpret_cast<uint4*>(&Ab[base + o])       = u0;               \
            *reinterpret_cast<uint4*>(&Ab[base + (o ^ 4)]) = u1;               \
        }                                                                      \
        {                                                                      \
            int r = srow;                                                      \
            uint4 u0 = make_uint4(f2tf32(raB[0].x), f2tf32(raB[1].x),          \
                                  f2tf32(raB[0].y), f2tf32(raB[1].y));         \
            uint4 u1 = make_uint4(f2tf32(raB[0].z), f2tf32(raB[1].z),          \
                                  f2tf32(raB[0].w), f2tf32(raB[1].w));         \
            int base = r * 32 + ((ss ^ (r & 3)) << 3);                         \
            int o = (r & 1) << 2;                                              \
            *reinterpret_cast<uint4*>(&Bb[base + o])       = u0;               \
            *reinterpret_cast<uint4*>(&Bb[base + (o ^ 4)]) = u1;               \
        }                                                                      \
    } while (0)

    FETCH(0);
    COMMIT(0);
    __syncthreads();

    const int aRow0 = (wm * 32 + g) * 32;        // float offsets
    const int bRow0 = (wn * 32 + g) * 32;

    for (int it = 0; it < KT; ++it) {
        const int b = it & 1;
        if (it + 1 < KT) FETCH((it + 1) * 32);

        const uint32_t* Ab = As + b * 4096;
        const uint32_t* Bb = Bs + b * 2048;
#pragma unroll
        for (int s = 0; s < 4; s++) {
            const int so = ((s ^ g3) << 3) + tq;
            uint32_t af[2][4];
#pragma unroll
            for (int mt = 0; mt < 2; mt++) {
                uint2 lo = *reinterpret_cast<const uint2*>(
                    &Ab[aRow0 + mt * 512 + so]);
                uint2 hi = *reinterpret_cast<const uint2*>(
                    &Ab[aRow0 + mt * 512 + 256 + so]);
                af[mt][0] = lo.x; af[mt][1] = hi.x;
                af[mt][2] = lo.y; af[mt][3] = hi.y;
            }
            uint32_t bf[4][2];
#pragma unroll
            for (int nt = 0; nt < 4; nt++) {
                uint2 bu = *reinterpret_cast<const uint2*>(
                    &Bb[bRow0 + nt * 256 + so]);
                bf[nt][0] = bu.x; bf[nt][1] = bu.y;
            }
#pragma unroll
            for (int mt = 0; mt < 2; mt++)
#pragma unroll
                for (int nt = 0; nt < 4; nt++)
                    mma_tf32(acc[mt][nt], af[mt], bf[nt]);
        }
        __syncthreads();

        if (it + 1 < KT) {
            COMMIT(1 - b);
            __syncthreads();
        }
    }

    // ---- epilogue ----
#pragma unroll
    for (int mt = 0; mt < 2; mt++) {
        int row0 = m0 + wm * 32 + mt * 16 + g;
#pragma unroll
        for (int nt = 0; nt < 4; nt++) {
            int col = n0 + wn * 32 + nt * 8 + t * 2;
#pragma unroll
            for (int half = 0; half < 2; half++) {
                int gm = row0 + half * 8;
                if (gm >= M) continue;
#pragma unroll
                for (int cc = 0; cc < 2; cc++) {
                    int gn = col + cc;
                    if (gn >= N) continue;
                    float bval = (BMODE == 1)
                               ? (gn < EQ ? bias0[gn] : bias1[gn - EQ])
                               : bias0[gn];
                    float v = (acc[mt][nt][half * 2 + cc] + bval) * alpha;
                    if (RELU) v = fmaxf(v, 0.f);
                    C[(size_t)gm * ldc + gn] = v;
                }
            }
        }
    }
#undef FETCH
#undef COMMIT
}

// ---------------------------------------------------------------------------
// Attention prop0: per node, 2 heads, 10x10, hd=136
// ---------------------------------------------------------------------------
__global__ void __launch_bounds__(256)
attn0_kernel(const float* __restrict__ qp, const float* __restrict__ kvp,
             float* __restrict__ o)
{
    __shared__ float Qs[NB][EQ];
    __shared__ float Ks[NB][EQ];
    __shared__ float Vs[NB][EQ];
    __shared__ float P[2][NB][NB];

    const int s = blockIdx.x;
    const int tid = threadIdx.x;
    const size_t base = (size_t)s * NB;

    for (int i = tid; i < NB * EQ; i += 256) {
        int r = i / EQ, f = i - r * EQ;
        Qs[r][f] = qp[(base + r) * EQ + f];
        Ks[r][f] = kvp[(base + r) * 544 + f];
        Vs[r][f] = kvp[(base + r) * 544 + EQ + f];
    }
    __syncthreads();

    if (tid < 200) {
        int h = tid / 100, rem = tid - h * 100;
        int qi = rem / NB, ki = rem - qi * NB;
        const float* q = &Qs[qi][h * HD];
        const float* k = &Ks[ki][h * HD];
        float acc = 0.f;
#pragma unroll 8
        for (int d = 0; d < HD; d++) acc = fmaf(q[d], k[d], acc);
        P[h][qi][ki] = acc;
    }
    __syncthreads();

    if (tid < 20) {
        int h = tid / NB, qi = tid - h * NB;
        float mx = -1e30f;
#pragma unroll
        for (int ki = 0; ki < NB; ki++) mx = fmaxf(mx, P[h][qi][ki]);
        float sum = 0.f;
#pragma unroll
        for (int ki = 0; ki < NB; ki++) {
            float e = expf(P[h][qi][ki] - mx);
            P[h][qi][ki] = e;
            sum += e;
        }
        float inv = 1.f / sum;
#pragma unroll
        for (int ki = 0; ki < NB; ki++) P[h][qi][ki] *= inv;
    }
    __syncthreads();

    for (int i = tid; i < NB * EQ; i += 256) {
        int qi = i / EQ, f = i - qi * EQ;
        int h = f / HD;
        float acc = 0.f;
#pragma unroll
        for (int ki = 0; ki < NB; ki++) acc = fmaf(P[h][qi][ki], Vs[ki][f], acc);
        o[(base + qi) * EQ + f] = acc;
    }
}

// ---------------------------------------------------------------------------
// Attention prop1: full 2048x2048, flash-style online softmax
// ---------------------------------------------------------------------------
#define A1_BQ   32
#define A1_BK   64
#define A1_KP   137
#define A1_PP   65
#define A1_SMEM_FLOATS (A1_BQ*HD + 2*A1_BK*A1_KP + A1_BQ*A1_PP + 3*A1_BQ)

__global__ void __launch_bounds__(256)
attn1_kernel(const float* __restrict__ qp, const float* __restrict__ kvp,
             float* __restrict__ o)
{
    extern __shared__ float sm[];
    float* Qs = sm;
    float* Ksm = Qs + A1_BQ * HD;
    float* Vsm = Ksm + A1_BK * A1_KP;
    float* Ps  = Vsm + A1_BK * A1_KP;
    float* m_s = Ps + A1_BQ * A1_PP;
    float* l_s = m_s + A1_BQ;
    float* al_s = l_s + A1_BQ;

    const int h  = blockIdx.y;
    const int q0 = blockIdx.x * A1_BQ;
    const int tid = threadIdx.x;

    for (int i = tid; i < A1_BQ * HD; i += 256) {
        int r = i / HD, d = i - r * HD;
        Qs[r * HD + d] = qp[(size_t)(q0 + r) * EQ + h * HD + d];
    }
    if (tid < A1_BQ) { m_s[tid] = -1e30f; l_s[tid] = 0.f; }

    const int qown = tid >> 3;
    const int dg   = tid & 7;
    const int tyq  = tid >> 5;
    const int txk  = tid & 31;

    float oacc[17];
#pragma unroll
    for (int j = 0; j < 17; j++) oacc[j] = 0.f;

    for (int kt = 0; kt < SRC; kt += A1_BK) {
        __syncthreads();
        for (int i = tid; i < A1_BK * HD; i += 256) {
            int r = i / HD, d = i - r * HD;
            Ksm[r * A1_KP + d] = kvp[(size_t)(kt + r) * 544 + h * HD + d];
            Vsm[r * A1_KP + d] = kvp[(size_t)(kt + r) * 544 + EQ + h * HD + d];
        }
        __syncthreads();

        float sc[4][2];
#pragma unroll
        for (int i = 0; i < 4; i++) { sc[i][0] = 0.f; sc[i][1] = 0.f; }
        const float* krow0 = &Ksm[(txk * 2 + 0) * A1_KP];
        const float* krow1 = &Ksm[(txk * 2 + 1) * A1_KP];
#pragma unroll 4
        for (int d = 0; d < HD; d++) {
            float kv0 = krow0[d];
            float kv1 = krow1[d];
#pragma unroll
            for (int i = 0; i < 4; i++) {
                float qv = Qs[(tyq * 4 + i) * HD + d];
                sc[i][0] = fmaf(qv, kv0, sc[i][0]);
                sc[i][1] = fmaf(qv, kv1, sc[i][1]);
            }
        }
#pragma unroll
        for (int i = 0; i < 4; i++) {
            Ps[(tyq * 4 + i) * A1_PP + txk * 2 + 0] = sc[i][0];
            Ps[(tyq * 4 + i) * A1_PP + txk * 2 + 1] = sc[i][1];
        }
        __syncthreads();

        if (tid < A1_BQ) {
            float mx = m_s[tid];
            float* prow = &Ps[tid * A1_PP];
#pragma unroll 8
            for (int j = 0; j < A1_BK; j++) mx = fmaxf(mx, prow[j]);
            float al = expf(m_s[tid] - mx);
            float sum = 0.f;
#pragma unroll 8
            for (int j = 0; j < A1_BK; j++) {
                float e = expf(prow[j] - mx);
                prow[j] = e;
                sum += e;
            }
            l_s[tid] = l_s[tid] * al + sum;
            m_s[tid] = mx;
            al_s[tid] = al;
        }
        __syncthreads();

        float al = al_s[qown];
#pragma unroll
        for (int j = 0; j < 17; j++) oacc[j] *= al;
        const float* prow = &Ps[qown * A1_PP];
#pragma unroll 2
        for (int ki = 0; ki < A1_BK; ki++) {
            float p = prow[ki];
            const float* vrow = &Vsm[ki * A1_KP + dg * 17];
#pragma unroll
            for (int j = 0; j < 17; j++) oacc[j] = fmaf(p, vrow[j], oacc[j]);
        }
    }

    float inv = 1.f / l_s[qown];
#pragma unroll
    for (int j = 0; j < 17; j++)
        o[(size_t)(q0 + qown) * EQ + h * HD + dg * 17 + j] = oacc[j] * inv;
}

// ---------------------------------------------------------------------------
// Host launch
// ---------------------------------------------------------------------------
extern "C" void kernel_launch(void* const* d_in, const int* in_sizes, int n_in,
                              void* d_out, int out_size)
{
    const float* emb0  = (const float*)d_in[0];
    const float* edge0 = (const float*)d_in[1];
    const float* td0   = (const float*)d_in[2];
    const float* emb1  = (const float*)d_in[3];
    const float* edge1 = (const float*)d_in[4];
    const float* td1   = (const float*)d_in[5];
    const float* emb2  = (const float*)d_in[6];
    const float* Wq    = (const float*)d_in[7];
    const float* bq    = (const float*)d_in[8];
    const float* Wk    = (const float*)d_in[9];
    const float* bk    = (const float*)d_in[10];
    const float* Wv    = (const float*)d_in[11];
    const float* bv    = (const float*)d_in[12];
    const float* Wo    = (const float*)d_in[13];
    const float* bo    = (const float*)d_in[14];
    const float* W1    = (const float*)d_in[15];
    const float* b1    = (const float*)d_in[16];
    const float* W2    = (const float*)d_in[17];
    const float* b2    = (const float*)d_in[18];
    float* out = (float*)d_out;

    float *kvp0, *qp0, *o0, *a0, *h0, *kvp1, *qp1, *o1, *a1, *h1;
    cudaGetSymbolAddress((void**)&kvp0, g_kvp0);
    cudaGetSymbolAddress((void**)&qp0,  g_qp0);
    cudaGetSymbolAddress((void**)&o0,   g_o0);
    cudaGetSymbolAddress((void**)&a0,   g_a0);
    cudaGetSymbolAddress((void**)&h0,   g_h0);
    cudaGetSymbolAddress((void**)&kvp1, g_kvp1);
    cudaGetSymbolAddress((void**)&qp1,  g_qp1);
    cudaGetSymbolAddress((void**)&o1,   g_o1);
    cudaGetSymbolAddress((void**)&a1,   g_a1);
    cudaGetSymbolAddress((void**)&h1,   g_h1);

    const float scale = 1.0f / sqrtf((float)HD);
    const int smem1 = A1_SMEM_FLOATS * (int)sizeof(float);
    cudaFuncSetAttribute(attn1_kernel,
                         cudaFuncAttributeMaxDynamicSharedMemorySize, smem1);
    cudaFuncSetAttribute(gemm_mma<1, 1, false>,
                         cudaFuncAttributeMaxDynamicSharedMemorySize, GM_SMEM);
    cudaFuncSetAttribute(gemm_mma<2, 0, false>,
                         cudaFuncAttributeMaxDynamicSharedMemorySize, GM_SMEM);
    cudaFuncSetAttribute(gemm_mma<0, 0, false>,
                         cudaFuncAttributeMaxDynamicSharedMemorySize, GM_SMEM);
    cudaFuncSetAttribute(gemm_mma<3, 0, true>,
                         cudaFuncAttributeMaxDynamicSharedMemorySize, GM_SMEM);

    // ---------------- propagation 0 ----------------
    // fused K/V projection: (20480 x 4440) x (4440 x 544)
    gemm_mma<1, 1, false><<<dim3(9, 160), 256, GM_SMEM>>>(
        emb0, edge0, td0, 0, Wk, Wv, KDT, bk, bv,
        kvp0, M0, 544, KDT, 544, 1.f);
    // Q projection
    gemm_mma<2, 0, false><<<dim3(5, 160), 256, GM_SMEM>>>(
        emb1, td1, nullptr, 0, Wq, nullptr, EQ, bq, nullptr,
        qp0, M0, EQ, EQ, EQ, scale);
    attn0_kernel<<<SRC, 256>>>(qp0, kvp0, o0);
    // output projection
    gemm_mma<0, 0, false><<<dim3(5, 160), 256, GM_SMEM>>>(
        o0, nullptr, nullptr, EQ, Wo, nullptr, EQ, bo, nullptr,
        a0, M0, EQ, EQ, EQ, 1.f);
    // FFN
    gemm_mma<3, 0, true><<<dim3(3, 160), 256, GM_SMEM>>>(
        a0, emb1, nullptr, 0, W1, nullptr, EQ + DDIM, b1, nullptr,
        h0, M0, DDIM, EQ + DDIM, DDIM, 1.f);
    gemm_mma<0, 0, false><<<dim3(3, 160), 256, GM_SMEM>>>(
        h0, nullptr, nullptr, DDIM, W2, nullptr, DDIM, b2, nullptr,
        out + OUT_R0, M0, DDIM, DDIM, DDIM, 1.f);

    // ---------------- propagation 1 ----------------
    gemm_mma<1, 1, false><<<dim3(9, 16), 256, GM_SMEM>>>(
        emb1, edge1, td1, 0, Wk, Wv, KDT, bk, bv,
        kvp1, M1, 544, KDT, 544, 1.f);
    // Q projection: q = [emb2, zeros(100)] -> only first 172 cols of Wq matter
    gemm_mma<0, 0, false><<<dim3(5, 16), 256, GM_SMEM>>>(
        emb2, nullptr, nullptr, DDIM, Wq, nullptr, EQ, bq, nullptr,
        qp1, M1, EQ, DDIM, EQ, scale);
    attn1_kernel<<<dim3(SRC / A1_BQ, 2), 256, smem1>>>(qp1, kvp1, o1);
    gemm_mma<0, 0, false><<<dim3(5, 16), 256, GM_SMEM>>>(
        o1, nullptr, nullptr, EQ, Wo, nullptr, EQ, bo, nullptr,
        a1, M1, EQ, EQ, EQ, 1.f);
    gemm_mma<3, 0, true><<<dim3(3, 16), 256, GM_SMEM>>>(
        a1, emb2, nullptr, 0, W1, nullptr, EQ + DDIM, b1, nullptr,
        h1, M1, DDIM, EQ + DDIM, DDIM, 1.f);
    gemm_mma<0, 0, false><<<dim3(3, 16), 256, GM_SMEM>>>(
        h1, nullptr, nullptr, DDIM, W2, nullptr, DDIM, b2, nullptr,
        out + OUT_R1, M1, DDIM, DDIM, DDIM, 1.f);

    // ---------------- passthrough outputs ----------------
    cudaMemcpyAsync(out + OUT_EDGE, edge1, (size_t)SRC * NB * EDIM * sizeof(float),
                    cudaMemcpyDeviceToDevice);
    cudaMemcpyAsync(out + OUT_TD, td1, (size_t)SRC * NB * TDIM * sizeof(float),
                    cudaMemcpyDeviceToDevice);
}

// round 5
// speedup vs baseline: 1.2074x; 1.2074x over previous
#include <cuda_runtime.h>
#include <math.h>
#include <stdint.h>

// ---------------------------------------------------------------------------
// Problem constants
// ---------------------------------------------------------------------------
#define SRC   2048          // S
#define NB    10            // neighbors
#define DDIM  172           // D
#define EDIM  172           // EDGE
#define TDIM  100           // TD
#define EQ    272           // E  = D + TD
#define KD    444           // D + EDGE + TD
#define KDT   4440          // KD * N
#define HD    136           // head dim (E / H)

#define M0    (SRC*NB)      // 20480 rows prop0
#define M1    SRC           // 2048  rows prop1

// output layout offsets (float elements)
#define OUT_R0    0
#define OUT_R1    (SRC*NB*DDIM)
#define OUT_EDGE  (OUT_R1 + SRC*DDIM)
#define OUT_TD    (OUT_EDGE + SRC*NB*EDIM)

// ---------------------------------------------------------------------------
// Scratch (device globals; no allocation allowed)
// ---------------------------------------------------------------------------
__device__ float g_kvp0[M0 * 544];
__device__ float g_qp0 [M0 * EQ];
__device__ float g_o0  [M0 * EQ];
__device__ float g_a0  [M0 * EQ];
__device__ float g_h0  [M0 * DDIM];
__device__ float g_kvp1[M1 * 544];
__device__ float g_qp1 [M1 * EQ];
__device__ float g_o1  [M1 * EQ];
__device__ float g_a1  [M1 * EQ];
__device__ float g_h1  [M1 * DDIM];

// ---------------------------------------------------------------------------
// A/B gather functors (float4-aligned; all segment boundaries %4 == 0)
//   AMODE 0: dense A0[row*lda + k]
//   AMODE 1: concat3 per-neighbor: emb(172)|edge(172)|td(100), KD=444, NB=10
//   AMODE 2: concat2 emb1(172)|td1(100)
//   AMODE 3: concat2 attn_out(272)|emb(172)
// ---------------------------------------------------------------------------
template<int MODE>
__device__ __forceinline__ float4 loadA(const float* __restrict__ A0,
                                        const float* __restrict__ A1,
                                        const float* __restrict__ A2,
                                        int lda, int row, int k)
{
    if (MODE == 0) {
        return *reinterpret_cast<const float4*>(A0 + (size_t)row * lda + k);
    } else if (MODE == 1) {
        int n2 = k / KD;
        int f  = k - n2 * KD;
        size_t sub = (size_t)row * NB + n2;
        if (f < DDIM)        return *reinterpret_cast<const float4*>(A0 + sub * DDIM + f);
        else if (f < 2*DDIM) return *reinterpret_cast<const float4*>(A1 + sub * EDIM + (f - DDIM));
        else                 return *reinterpret_cast<const float4*>(A2 + sub * TDIM + (f - 2*DDIM));
    } else if (MODE == 2) {
        if (k < DDIM) return *reinterpret_cast<const float4*>(A0 + (size_t)row * DDIM + k);
        else          return *reinterpret_cast<const float4*>(A1 + (size_t)row * TDIM + (k - DDIM));
    } else { // MODE == 3
        if (k < EQ)   return *reinterpret_cast<const float4*>(A0 + (size_t)row * EQ + k);
        else          return *reinterpret_cast<const float4*>(A1 + (size_t)row * DDIM + (k - EQ));
    }
}

// BMODE 0: dense B0[n*ldb + k]; BMODE 1: rows split at n=272 (Wk|Wv), ldb=KDT
template<int MODE>
__device__ __forceinline__ float4 loadB(const float* __restrict__ B0,
                                        const float* __restrict__ B1,
                                        int ldb, int n, int k)
{
    if (MODE == 0) {
        return *reinterpret_cast<const float4*>(B0 + (size_t)n * ldb + k);
    } else {
        if (n < EQ) return *reinterpret_cast<const float4*>(B0 + (size_t)n * KDT + k);
        else        return *reinterpret_cast<const float4*>(B1 + (size_t)(n - EQ) * KDT + k);
    }
}

// ---------------------------------------------------------------------------
// tf32 helpers
// ---------------------------------------------------------------------------
__device__ __forceinline__ uint32_t f2tf32(float f) {
    uint32_t u;
    asm("cvt.rna.tf32.f32 %0, %1;" : "=r"(u) : "f"(f));
    return u;
}

__device__ __forceinline__ void mma_tf32(float c[4], const uint32_t a[4],
                                         const uint32_t b[2]) {
    asm volatile(
        "mma.sync.aligned.m16n8k8.row.col.f32.tf32.tf32.f32 "
        "{%0,%1,%2,%3}, {%4,%5,%6,%7}, {%8,%9}, {%0,%1,%2,%3};"
        : "+f"(c[0]), "+f"(c[1]), "+f"(c[2]), "+f"(c[3])
        : "r"(a[0]), "r"(a[1]), "r"(a[2]), "r"(a[3]), "r"(b[0]), "r"(b[1]));
}

// ---------------------------------------------------------------------------
// mma.sync tf32 GEMM:  C[m,n] = act((sum_k A[m,k]*B[n,k] + bias[n]) * alpha)
// CTA tile 128x64xBK32, 256 threads (8 warps, 4x2), warp tile 32x32.
// Double-buffered SMEM, register prefetch, SINGLE __syncthreads per k-tile
// (STS of next tile overlaps MMA of current tile).
// SMEM: As[2][128][36] + Bs[2][64][36] floats (tf32 bit patterns).
// ---------------------------------------------------------------------------
#define APAD 36
#define GM_SMEM ((2*128*APAD + 2*64*APAD) * 4)   // 55296 bytes

template<int AMODE, int BMODE, bool RELU>
__global__ void __launch_bounds__(256)
gemm_mma(const float* __restrict__ A0, const float* __restrict__ A1,
         const float* __restrict__ A2, int lda,
         const float* __restrict__ B0, const float* __restrict__ B1, int ldb,
         const float* __restrict__ bias0, const float* __restrict__ bias1,
         float* __restrict__ C, int M, int N, int K, int ldc, float alpha)
{
    extern __shared__ float sh[];
    float* As = sh;                      // [2][128][APAD]
    float* Bs = sh + 2 * 128 * APAD;     // [2][64][APAD]

    const int tid  = threadIdx.x;
    const int wid  = tid >> 5;
    const int lane = tid & 31;
    const int g    = lane >> 2;      // group 0..7
    const int t    = lane & 3;       // thread in group
    const int wm   = wid & 3;        // warp m position (0..3) x32 rows
    const int wn   = wid >> 2;       // warp n position (0..1) x32 cols
    const int m0   = blockIdx.y * 128;
    const int n0   = blockIdx.x * 64;

    float acc[2][4][4];
#pragma unroll
    for (int i = 0; i < 2; i++)
#pragma unroll
        for (int j = 0; j < 4; j++)
#pragma unroll
            for (int l = 0; l < 4; l++) acc[i][j][l] = 0.f;

    // staging decomposition (fixed per thread)
    const int ar  = tid >> 3;            // +32 per step: rows of A (4 steps)
    const int akq = tid & 7;             // k quad
    const int KT  = (K + 31) / 32;

    float4 ra[4], rb[2];

#define FETCH(k0_)                                                             \
    do {                                                                       \
        const int gk = (k0_) + akq * 4;                                        \
        _Pragma("unroll")                                                      \
        for (int p = 0; p < 4; p++) {                                          \
            int r = ar + p * 32;                                               \
            ra[p] = (gk < K) ? loadA<AMODE>(A0, A1, A2, lda, m0 + r, gk)       \
                             : make_float4(0.f, 0.f, 0.f, 0.f);                \
        }                                                                      \
        _Pragma("unroll")                                                      \
        for (int p = 0; p < 2; p++) {                                          \
            int r = ar + p * 32, gn = n0 + r;                                  \
            rb[p] = (gn < N && gk < K) ? loadB<BMODE>(B0, B1, ldb, gn, gk)     \
                                       : make_float4(0.f, 0.f, 0.f, 0.f);      \
        }                                                                      \
    } while (0)

#define COMMIT(buf_)                                                           \
    do {                                                                       \
        float* Ab2 = As + (buf_) * 128 * APAD;                                 \
        float* Bb2 = Bs + (buf_) * 64 * APAD;                                  \
        _Pragma("unroll")                                                      \
        for (int p = 0; p < 4; p++) {                                          \
            uint32_t* d = reinterpret_cast<uint32_t*>(                         \
                &Ab2[(ar + p*32) * APAD + akq*4]);                             \
            d[0] = f2tf32(ra[p].x); d[1] = f2tf32(ra[p].y);                    \
            d[2] = f2tf32(ra[p].z); d[3] = f2tf32(ra[p].w);                    \
        }                                                                      \
        _Pragma("unroll")                                                      \
        for (int p = 0; p < 2; p++) {                                          \
            uint32_t* d = reinterpret_cast<uint32_t*>(                         \
                &Bb2[(ar + p*32) * APAD + akq*4]);                             \
            d[0] = f2tf32(rb[p].x); d[1] = f2tf32(rb[p].y);                    \
            d[2] = f2tf32(rb[p].z); d[3] = f2tf32(rb[p].w);                    \
        }                                                                      \
    } while (0)

    FETCH(0);
    COMMIT(0);
    __syncthreads();

    for (int it = 0; it < KT; ++it) {
        const int b = it & 1;
        // prefetch next tile into registers (overlaps compute below)
        if (it + 1 < KT) FETCH((it + 1) * 32);

        // compute on buffer b
        const float* Ab = As + b * 128 * APAD;
        const float* Bb = Bs + b * 64 * APAD;
#pragma unroll
        for (int ks = 0; ks < 4; ks++) {
            const int kb = ks * 8;
            uint32_t af[2][4];
#pragma unroll
            for (int mt = 0; mt < 2; mt++) {
                int row = wm * 32 + mt * 16 + g;
                af[mt][0] = reinterpret_cast<const uint32_t*>(Ab)[row * APAD + kb + t];
                af[mt][1] = reinterpret_cast<const uint32_t*>(Ab)[(row + 8) * APAD + kb + t];
                af[mt][2] = reinterpret_cast<const uint32_t*>(Ab)[row * APAD + kb + t + 4];
                af[mt][3] = reinterpret_cast<const uint32_t*>(Ab)[(row + 8) * APAD + kb + t + 4];
            }
            uint32_t bf[4][2];
#pragma unroll
            for (int nt = 0; nt < 4; nt++) {
                int rn = wn * 32 + nt * 8 + g;
                bf[nt][0] = reinterpret_cast<const uint32_t*>(Bb)[rn * APAD + kb + t];
                bf[nt][1] = reinterpret_cast<const uint32_t*>(Bb)[rn * APAD + kb + t + 4];
            }
#pragma unroll
            for (int mt = 0; mt < 2; mt++)
#pragma unroll
                for (int nt = 0; nt < 4; nt++)
                    mma_tf32(acc[mt][nt], af[mt], bf[nt]);
        }

        // commit prefetched tile to the other buffer (overlaps with other
        // warps' MMAs; buffer 1-b was last read two iterations ago, and all
        // warps passed the barrier after that read)
        if (it + 1 < KT) COMMIT(1 - b);
        __syncthreads();
    }

    // ---- epilogue ----
#pragma unroll
    for (int mt = 0; mt < 2; mt++) {
        int row0 = m0 + wm * 32 + mt * 16 + g;
#pragma unroll
        for (int nt = 0; nt < 4; nt++) {
            int col = n0 + wn * 32 + nt * 8 + t * 2;
#pragma unroll
            for (int half = 0; half < 2; half++) {
                int gm = row0 + half * 8;
                if (gm >= M) continue;
#pragma unroll
                for (int cc = 0; cc < 2; cc++) {
                    int gn = col + cc;
                    if (gn >= N) continue;
                    float bval = (BMODE == 1)
                               ? (gn < EQ ? bias0[gn] : bias1[gn - EQ])
                               : bias0[gn];
                    float v = (acc[mt][nt][half * 2 + cc] + bval) * alpha;
                    if (RELU) v = fmaxf(v, 0.f);
                    C[(size_t)gm * ldc + gn] = v;
                }
            }
        }
    }
#undef FETCH
#undef COMMIT
}

// ---------------------------------------------------------------------------
// Attention prop0: per node, 2 heads, 10x10, hd=136
// ---------------------------------------------------------------------------
__global__ void __launch_bounds__(256)
attn0_kernel(const float* __restrict__ qp, const float* __restrict__ kvp,
             float* __restrict__ o)
{
    __shared__ float Qs[NB][EQ];
    __shared__ float Ks[NB][EQ];
    __shared__ float Vs[NB][EQ];
    __shared__ float P[2][NB][NB];

    const int s = blockIdx.x;
    const int tid = threadIdx.x;
    const size_t base = (size_t)s * NB;

    for (int i = tid; i < NB * EQ; i += 256) {
        int r = i / EQ, f = i - r * EQ;
        Qs[r][f] = qp[(base + r) * EQ + f];
        Ks[r][f] = kvp[(base + r) * 544 + f];
        Vs[r][f] = kvp[(base + r) * 544 + EQ + f];
    }
    __syncthreads();

    if (tid < 200) {
        int h = tid / 100, rem = tid - h * 100;
        int qi = rem / NB, ki = rem - qi * NB;
        const float* q = &Qs[qi][h * HD];
        const float* k = &Ks[ki][h * HD];
        float acc = 0.f;
#pragma unroll 8
        for (int d = 0; d < HD; d++) acc = fmaf(q[d], k[d], acc);
        P[h][qi][ki] = acc;
    }
    __syncthreads();

    if (tid < 20) {
        int h = tid / NB, qi = tid - h * NB;
        float mx = -1e30f;
#pragma unroll
        for (int ki = 0; ki < NB; ki++) mx = fmaxf(mx, P[h][qi][ki]);
        float sum = 0.f;
#pragma unroll
        for (int ki = 0; ki < NB; ki++) {
            float e = expf(P[h][qi][ki] - mx);
            P[h][qi][ki] = e;
            sum += e;
        }
        float inv = 1.f / sum;
#pragma unroll
        for (int ki = 0; ki < NB; ki++) P[h][qi][ki] *= inv;
    }
    __syncthreads();

    for (int i = tid; i < NB * EQ; i += 256) {
        int qi = i / EQ, f = i - qi * EQ;
        int h = f / HD;
        float acc = 0.f;
#pragma unroll
        for (int ki = 0; ki < NB; ki++) acc = fmaf(P[h][qi][ki], Vs[ki][f], acc);
        o[(base + qi) * EQ + f] = acc;
    }
}

// ---------------------------------------------------------------------------
// Attention prop1: full 2048x2048, flash-style online softmax
// ---------------------------------------------------------------------------
#define A1_BQ   32
#define A1_BK   64
#define A1_KP   137
#define A1_PP   65
#define A1_SMEM_FLOATS (A1_BQ*HD + 2*A1_BK*A1_KP + A1_BQ*A1_PP + 3*A1_BQ)

__global__ void __launch_bounds__(256)
attn1_kernel(const float* __restrict__ qp, const float* __restrict__ kvp,
             float* __restrict__ o)
{
    extern __shared__ float sm[];
    float* Qs = sm;
    float* Ksm = Qs + A1_BQ * HD;
    float* Vsm = Ksm + A1_BK * A1_KP;
    float* Ps  = Vsm + A1_BK * A1_KP;
    float* m_s = Ps + A1_BQ * A1_PP;
    float* l_s = m_s + A1_BQ;
    float* al_s = l_s + A1_BQ;

    const int h  = blockIdx.y;
    const int q0 = blockIdx.x * A1_BQ;
    const int tid = threadIdx.x;

    for (int i = tid; i < A1_BQ * HD; i += 256) {
        int r = i / HD, d = i - r * HD;
        Qs[r * HD + d] = qp[(size_t)(q0 + r) * EQ + h * HD + d];
    }
    if (tid < A1_BQ) { m_s[tid] = -1e30f; l_s[tid] = 0.f; }

    const int qown = tid >> 3;
    const int dg   = tid & 7;
    const int tyq  = tid >> 5;
    const int txk  = tid & 31;

    float oacc[17];
#pragma unroll
    for (int j = 0; j < 17; j++) oacc[j] = 0.f;

    for (int kt = 0; kt < SRC; kt += A1_BK) {
        __syncthreads();
        for (int i = tid; i < A1_BK * HD; i += 256) {
            int r = i / HD, d = i - r * HD;
            Ksm[r * A1_KP + d] = kvp[(size_t)(kt + r) * 544 + h * HD + d];
            Vsm[r * A1_KP + d] = kvp[(size_t)(kt + r) * 544 + EQ + h * HD + d];
        }
        __syncthreads();

        float sc[4][2];
#pragma unroll
        for (int i = 0; i < 4; i++) { sc[i][0] = 0.f; sc[i][1] = 0.f; }
        const float* krow0 = &Ksm[(txk * 2 + 0) * A1_KP];
        const float* krow1 = &Ksm[(txk * 2 + 1) * A1_KP];
#pragma unroll 4
        for (int d = 0; d < HD; d++) {
            float kv0 = krow0[d];
            float kv1 = krow1[d];
#pragma unroll
            for (int i = 0; i < 4; i++) {
                float qv = Qs[(tyq * 4 + i) * HD + d];
                sc[i][0] = fmaf(qv, kv0, sc[i][0]);
                sc[i][1] = fmaf(qv, kv1, sc[i][1]);
            }
        }
#pragma unroll
        for (int i = 0; i < 4; i++) {
            Ps[(tyq * 4 + i) * A1_PP + txk * 2 + 0] = sc[i][0];
            Ps[(tyq * 4 + i) * A1_PP + txk * 2 + 1] = sc[i][1];
        }
        __syncthreads();

        if (tid < A1_BQ) {
            float mx = m_s[tid];
            float* prow = &Ps[tid * A1_PP];
#pragma unroll 8
            for (int j = 0; j < A1_BK; j++) mx = fmaxf(mx, prow[j]);
            float al = expf(m_s[tid] - mx);
            float sum = 0.f;
#pragma unroll 8
            for (int j = 0; j < A1_BK; j++) {
                float e = expf(prow[j] - mx);
                prow[j] = e;
                sum += e;
            }
            l_s[tid] = l_s[tid] * al + sum;
            m_s[tid] = mx;
            al_s[tid] = al;
        }
        __syncthreads();

        float al = al_s[qown];
#pragma unroll
        for (int j = 0; j < 17; j++) oacc[j] *= al;
        const float* prow = &Ps[qown * A1_PP];
#pragma unroll 2
        for (int ki = 0; ki < A1_BK; ki++) {
            float p = prow[ki];
            const float* vrow = &Vsm[ki * A1_KP + dg * 17];
#pragma unroll
            for (int j = 0; j < 17; j++) oacc[j] = fmaf(p, vrow[j], oacc[j]);
        }
    }

    float inv = 1.f / l_s[qown];
#pragma unroll
    for (int j = 0; j < 17; j++)
        o[(size_t)(q0 + qown) * EQ + h * HD + dg * 17 + j] = oacc[j] * inv;
}

// ---------------------------------------------------------------------------
// Host launch
// ---------------------------------------------------------------------------
extern "C" void kernel_launch(void* const* d_in, const int* in_sizes, int n_in,
                              void* d_out, int out_size)
{
    const float* emb0  = (const float*)d_in[0];
    const float* edge0 = (const float*)d_in[1];
    const float* td0   = (const float*)d_in[2];
    const float* emb1  = (const float*)d_in[3];
    const float* edge1 = (const float*)d_in[4];
    const float* td1   = (const float*)d_in[5];
    const float* emb2  = (const float*)d_in[6];
    const float* Wq    = (const float*)d_in[7];
    const float* bq    = (const float*)d_in[8];
    const float* Wk    = (const float*)d_in[9];
    const float* bk    = (const float*)d_in[10];
    const float* Wv    = (const float*)d_in[11];
    const float* bv    = (const float*)d_in[12];
    const float* Wo    = (const float*)d_in[13];
    const float* bo    = (const float*)d_in[14];
    const float* W1    = (const float*)d_in[15];
    const float* b1    = (const float*)d_in[16];
    const float* W2    = (const float*)d_in[17];
    const float* b2    = (const float*)d_in[18];
    float* out = (float*)d_out;

    float *kvp0, *qp0, *o0, *a0, *h0, *kvp1, *qp1, *o1, *a1, *h1;
    cudaGetSymbolAddress((void**)&kvp0, g_kvp0);
    cudaGetSymbolAddress((void**)&qp0,  g_qp0);
    cudaGetSymbolAddress((void**)&o0,   g_o0);
    cudaGetSymbolAddress((void**)&a0,   g_a0);
    cudaGetSymbolAddress((void**)&h0,   g_h0);
    cudaGetSymbolAddress((void**)&kvp1, g_kvp1);
    cudaGetSymbolAddress((void**)&qp1,  g_qp1);
    cudaGetSymbolAddress((void**)&o1,   g_o1);
    cudaGetSymbolAddress((void**)&a1,   g_a1);
    cudaGetSymbolAddress((void**)&h1,   g_h1);

    const float scale = 1.0f / sqrtf((float)HD);
    const int smem1 = A1_SMEM_FLOATS * (int)sizeof(float);
    cudaFuncSetAttribute(attn1_kernel,
                         cudaFuncAttributeMaxDynamicSharedMemorySize, smem1);
    cudaFuncSetAttribute(gemm_mma<1, 1, false>,
                         cudaFuncAttributeMaxDynamicSharedMemorySize, GM_SMEM);
    cudaFuncSetAttribute(gemm_mma<2, 0, false>,
                         cudaFuncAttributeMaxDynamicSharedMemorySize, GM_SMEM);
    cudaFuncSetAttribute(gemm_mma<0, 0, false>,
                         cudaFuncAttributeMaxDynamicSharedMemorySize, GM_SMEM);
    cudaFuncSetAttribute(gemm_mma<3, 0, true>,
                         cudaFuncAttributeMaxDynamicSharedMemorySize, GM_SMEM);

    // ---------------- propagation 0 ----------------
    // fused K/V projection: (20480 x 4440) x (4440 x 544)
    gemm_mma<1, 1, false><<<dim3(9, 160), 256, GM_SMEM>>>(
        emb0, edge0, td0, 0, Wk, Wv, KDT, bk, bv,
        kvp0, M0, 544, KDT, 544, 1.f);
    // Q projection
    gemm_mma<2, 0, false><<<dim3(5, 160), 256, GM_SMEM>>>(
        emb1, td1, nullptr, 0, Wq, nullptr, EQ, bq, nullptr,
        qp0, M0, EQ, EQ, EQ, scale);
    attn0_kernel<<<SRC, 256>>>(qp0, kvp0, o0);
    // output projection
    gemm_mma<0, 0, false><<<dim3(5, 160), 256, GM_SMEM>>>(
        o0, nullptr, nullptr, EQ, Wo, nullptr, EQ, bo, nullptr,
        a0, M0, EQ, EQ, EQ, 1.f);
    // FFN
    gemm_mma<3, 0, true><<<dim3(3, 160), 256, GM_SMEM>>>(
        a0, emb1, nullptr, 0, W1, nullptr, EQ + DDIM, b1, nullptr,
        h0, M0, DDIM, EQ + DDIM, DDIM, 1.f);
    gemm_mma<0, 0, false><<<dim3(3, 160), 256, GM_SMEM>>>(
        h0, nullptr, nullptr, DDIM, W2, nullptr, DDIM, b2, nullptr,
        out + OUT_R0, M0, DDIM, DDIM, DDIM, 1.f);

    // ---------------- propagation 1 ----------------
    gemm_mma<1, 1, false><<<dim3(9, 16), 256, GM_SMEM>>>(
        emb1, edge1, td1, 0, Wk, Wv, KDT, bk, bv,
        kvp1, M1, 544, KDT, 544, 1.f);
    // Q projection: q = [emb2, zeros(100)] -> only first 172 cols of Wq matter
    gemm_mma<0, 0, false><<<dim3(5, 16), 256, GM_SMEM>>>(
        emb2, nullptr, nullptr, DDIM, Wq, nullptr, EQ, bq, nullptr,
        qp1, M1, EQ, DDIM, EQ, scale);
    attn1_kernel<<<dim3(SRC / A1_BQ, 2), 256, smem1>>>(qp1, kvp1, o1);
    gemm_mma<0, 0, false><<<dim3(5, 16), 256, GM_SMEM>>>(
        o1, nullptr, nullptr, EQ, Wo, nullptr, EQ, bo, nullptr,
        a1, M1, EQ, EQ, EQ, 1.f);
    gemm_mma<3, 0, true><<<dim3(3, 16), 256, GM_SMEM>>>(
        a1, emb2, nullptr, 0, W1, nullptr, EQ + DDIM, b1, nullptr,
        h1, M1, DDIM, EQ + DDIM, DDIM, 1.f);
    gemm_mma<0, 0, false><<<dim3(3, 16), 256, GM_SMEM>>>(
        h1, nullptr, nullptr, DDIM, W2, nullptr, DDIM, b2, nullptr,
        out + OUT_R1, M1, DDIM, DDIM, DDIM, 1.f);

    // ---------------- passthrough outputs ----------------
    cudaMemcpyAsync(out + OUT_EDGE, edge1, (size_t)SRC * NB * EDIM * sizeof(float),
                    cudaMemcpyDeviceToDevice);
    cudaMemcpyAsync(out + OUT_TD, td1, (size_t)SRC * NB * TDIM * sizeof(float),
                    cudaMemcpyDeviceToDevice);
}

// round 6
// speedup vs baseline: 1.4558x; 1.2057x over previous
#include <cuda_runtime.h>
#include <cuda_fp16.h>
#include <math.h>
#include <stdint.h>

// ---------------------------------------------------------------------------
// Problem constants
// ---------------------------------------------------------------------------
#define SRC   2048          // S
#define NB    10            // neighbors
#define DDIM  172           // D
#define EDIM  172           // EDGE
#define TDIM  100           // TD
#define EQ    272           // E  = D + TD
#define KD    444           // D + EDGE + TD
#define KDT   4440          // KD * N
#define HD    136           // head dim (E / H)

#define M0    (SRC*NB)      // 20480 rows prop0
#define M1    SRC           // 2048  rows prop1

// output layout offsets (float elements)
#define OUT_R0    0
#define OUT_R1    (SRC*NB*DDIM)
#define OUT_EDGE  (OUT_R1 + SRC*DDIM)
#define OUT_TD    (OUT_EDGE + SRC*NB*EDIM)

// ---------------------------------------------------------------------------
// Scratch (device globals; no allocation allowed)
// ---------------------------------------------------------------------------
__device__ float g_kvp0[M0 * 544];
__device__ float g_qp0 [M0 * EQ];
__device__ float g_o0  [M0 * EQ];
__device__ float g_a0  [M0 * EQ];
__device__ float g_h0  [M0 * DDIM];
__device__ float g_kvp1[M1 * 544];
__device__ float g_qp1 [M1 * EQ];
__device__ float g_o1  [M1 * EQ];
__device__ float g_a1  [M1 * EQ];
__device__ float g_h1  [M1 * DDIM];

// ---------------------------------------------------------------------------
// A/B gather functors (float4-aligned; all segment boundaries %4 == 0)
//   AMODE 0: dense A0[row*lda + k]
//   AMODE 1: concat3 per-neighbor: emb(172)|edge(172)|td(100), KD=444, NB=10
//   AMODE 2: concat2 emb1(172)|td1(100)
//   AMODE 3: concat2 attn_out(272)|emb(172)
// ---------------------------------------------------------------------------
template<int MODE>
__device__ __forceinline__ float4 loadA(const float* __restrict__ A0,
                                        const float* __restrict__ A1,
                                        const float* __restrict__ A2,
                                        int lda, int row, int k)
{
    if (MODE == 0) {
        return *reinterpret_cast<const float4*>(A0 + (size_t)row * lda + k);
    } else if (MODE == 1) {
        int n2 = k / KD;
        int f  = k - n2 * KD;
        size_t sub = (size_t)row * NB + n2;
        if (f < DDIM)        return *reinterpret_cast<const float4*>(A0 + sub * DDIM + f);
        else if (f < 2*DDIM) return *reinterpret_cast<const float4*>(A1 + sub * EDIM + (f - DDIM));
        else                 return *reinterpret_cast<const float4*>(A2 + sub * TDIM + (f - 2*DDIM));
    } else if (MODE == 2) {
        if (k < DDIM) return *reinterpret_cast<const float4*>(A0 + (size_t)row * DDIM + k);
        else          return *reinterpret_cast<const float4*>(A1 + (size_t)row * TDIM + (k - DDIM));
    } else { // MODE == 3
        if (k < EQ)   return *reinterpret_cast<const float4*>(A0 + (size_t)row * EQ + k);
        else          return *reinterpret_cast<const float4*>(A1 + (size_t)row * DDIM + (k - EQ));
    }
}

// BMODE 0: dense B0[n*ldb + k]; BMODE 1: rows split at n=272 (Wk|Wv), ldb=KDT
template<int MODE>
__device__ __forceinline__ float4 loadB(const float* __restrict__ B0,
                                        const float* __restrict__ B1,
                                        int ldb, int n, int k)
{
    if (MODE == 0) {
        return *reinterpret_cast<const float4*>(B0 + (size_t)n * ldb + k);
    } else {
        if (n < EQ) return *reinterpret_cast<const float4*>(B0 + (size_t)n * KDT + k);
        else        return *reinterpret_cast<const float4*>(B1 + (size_t)(n - EQ) * KDT + k);
    }
}

// ---------------------------------------------------------------------------
// fp16 helpers
// ---------------------------------------------------------------------------
__device__ __forceinline__ uint32_t f2h2(float x, float y) {
    half2 h = __float22half2_rn(make_float2(x, y));
    return *reinterpret_cast<uint32_t*>(&h);
}

__device__ __forceinline__ void mma_f16(float c[4], const uint32_t a[4],
                                        const uint32_t b[2]) {
    asm volatile(
        "mma.sync.aligned.m16n8k16.row.col.f32.f16.f16.f32 "
        "{%0,%1,%2,%3}, {%4,%5,%6,%7}, {%8,%9}, {%0,%1,%2,%3};"
        : "+f"(c[0]), "+f"(c[1]), "+f"(c[2]), "+f"(c[3])
        : "r"(a[0]), "r"(a[1]), "r"(a[2]), "r"(a[3]), "r"(b[0]), "r"(b[1]));
}

// ---------------------------------------------------------------------------
// mma.sync fp16 GEMM (fp32 accumulate):
//   C[m,n] = act((sum_k A[m,k]*B[n,k] + bias[n]) * alpha)
// CTA tile 128x64xBK32, 256 threads (8 warps, 4x2), warp tile 32x32.
// MMA shape m16n8k16 -> per warp k-tile: 16 MMAs, 32 LDS.32 (was 32/64 tf32).
// SMEM rows: 16 half2 of data padded to stride 20 half2 (conflict-free:
// banks (20g + t [+4][+8]) mod 32 form a permutation for g=0..7, t=0..3).
// Single __syncthreads per k-tile; STS of next tile overlaps MMA.
// ---------------------------------------------------------------------------
#define HPAD 20   // half2 stride per row (16 data + 4 pad)
#define GM_SMEM ((2*128*HPAD + 2*64*HPAD) * 4)   // 30720 bytes

template<int AMODE, int BMODE, bool RELU>
__global__ void __launch_bounds__(256)
gemm_mma(const float* __restrict__ A0, const float* __restrict__ A1,
         const float* __restrict__ A2, int lda,
         const float* __restrict__ B0, const float* __restrict__ B1, int ldb,
         const float* __restrict__ bias0, const float* __restrict__ bias1,
         float* __restrict__ C, int M, int N, int K, int ldc, float alpha)
{
    extern __shared__ uint32_t sh[];          // half2 cells
    uint32_t* As = sh;                        // [2][128][HPAD]
    uint32_t* Bs = sh + 2 * 128 * HPAD;       // [2][64][HPAD]

    const int tid  = threadIdx.x;
    const int wid  = tid >> 5;
    const int lane = tid & 31;
    const int g    = lane >> 2;      // group 0..7
    const int t    = lane & 3;       // thread in group
    const int wm   = wid & 3;        // warp m position (0..3) x32 rows
    const int wn   = wid >> 2;       // warp n position (0..1) x32 cols
    const int m0   = blockIdx.y * 128;
    const int n0   = blockIdx.x * 64;

    float acc[2][4][4];
#pragma unroll
    for (int i = 0; i < 2; i++)
#pragma unroll
        for (int j = 0; j < 4; j++)
#pragma unroll
            for (int l = 0; l < 4; l++) acc[i][j][l] = 0.f;

    // staging decomposition (fixed per thread)
    const int ar  = tid >> 3;            // +32 per step: rows of A (4 steps)
    const int akq = tid & 7;             // k quad (4 floats = 2 half2)
    const int KT  = (K + 31) / 32;

    float4 ra[4], rb[2];

#define FETCH(k0_)                                                             \
    do {                                                                       \
        const int gk = (k0_) + akq * 4;                                        \
        _Pragma("unroll")                                                      \
        for (int p = 0; p < 4; p++) {                                          \
            int r = ar + p * 32;                                               \
            ra[p] = (gk < K) ? loadA<AMODE>(A0, A1, A2, lda, m0 + r, gk)       \
                             : make_float4(0.f, 0.f, 0.f, 0.f);                \
        }                                                                      \
        _Pragma("unroll")                                                      \
        for (int p = 0; p < 2; p++) {                                          \
            int r = ar + p * 32, gn = n0 + r;                                  \
            rb[p] = (gn < N && gk < K) ? loadB<BMODE>(B0, B1, ldb, gn, gk)     \
                                       : make_float4(0.f, 0.f, 0.f, 0.f);      \
        }                                                                      \
    } while (0)

#define COMMIT(buf_)                                                           \
    do {                                                                       \
        uint32_t* Ab2 = As + (buf_) * 128 * HPAD;                              \
        uint32_t* Bb2 = Bs + (buf_) * 64 * HPAD;                               \
        _Pragma("unroll")                                                      \
        for (int p = 0; p < 4; p++) {                                          \
            uint2 u = make_uint2(f2h2(ra[p].x, ra[p].y),                       \
                                 f2h2(ra[p].z, ra[p].w));                      \
            *reinterpret_cast<uint2*>(                                         \
                &Ab2[(ar + p*32) * HPAD + akq*2]) = u;                         \
        }                                                                      \
        _Pragma("unroll")                                                      \
        for (int p = 0; p < 2; p++) {                                          \
            uint2 u = make_uint2(f2h2(rb[p].x, rb[p].y),                       \
                                 f2h2(rb[p].z, rb[p].w));                      \
            *reinterpret_cast<uint2*>(                                         \
                &Bb2[(ar + p*32) * HPAD + akq*2]) = u;                         \
        }                                                                      \
    } while (0)

    FETCH(0);
    COMMIT(0);
    __syncthreads();

    for (int it = 0; it < KT; ++it) {
        const int b = it & 1;
        // prefetch next tile into registers (overlaps compute below)
        if (it + 1 < KT) FETCH((it + 1) * 32);

        // compute on buffer b: 2 k-steps of K=16 (8 half2 each)
        const uint32_t* Ab = As + b * 128 * HPAD;
        const uint32_t* Bb = Bs + b * 64 * HPAD;
#pragma unroll
        for (int ks = 0; ks < 2; ks++) {
            const int kb2 = ks * 8;          // half2 offset within row
            uint32_t af[2][4];
#pragma unroll
            for (int mt = 0; mt < 2; mt++) {
                int row = wm * 32 + mt * 16 + g;
                af[mt][0] = Ab[row * HPAD + kb2 + t];
                af[mt][1] = Ab[(row + 8) * HPAD + kb2 + t];
                af[mt][2] = Ab[row * HPAD + kb2 + t + 4];
                af[mt][3] = Ab[(row + 8) * HPAD + kb2 + t + 4];
            }
            uint32_t bf[4][2];
#pragma unroll
            for (int nt = 0; nt < 4; nt++) {
                int rn = wn * 32 + nt * 8 + g;
                bf[nt][0] = Bb[rn * HPAD + kb2 + t];
                bf[nt][1] = Bb[rn * HPAD + kb2 + t + 4];
            }
#pragma unroll
            for (int mt = 0; mt < 2; mt++)
#pragma unroll
                for (int nt = 0; nt < 4; nt++)
                    mma_f16(acc[mt][nt], af[mt], bf[nt]);
        }

        // commit prefetched tile to the other buffer (overlaps other warps'
        // MMAs; buffer 1-b was last read before the previous barrier)
        if (it + 1 < KT) COMMIT(1 - b);
        __syncthreads();
    }

    // ---- epilogue ----
#pragma unroll
    for (int mt = 0; mt < 2; mt++) {
        int row0 = m0 + wm * 32 + mt * 16 + g;
#pragma unroll
        for (int nt = 0; nt < 4; nt++) {
            int col = n0 + wn * 32 + nt * 8 + t * 2;
#pragma unroll
            for (int half = 0; half < 2; half++) {
                int gm = row0 + half * 8;
                if (gm >= M) continue;
#pragma unroll
                for (int cc = 0; cc < 2; cc++) {
                    int gn = col + cc;
                    if (gn >= N) continue;
                    float bval = (BMODE == 1)
                               ? (gn < EQ ? bias0[gn] : bias1[gn - EQ])
                               : bias0[gn];
                    float v = (acc[mt][nt][half * 2 + cc] + bval) * alpha;
                    if (RELU) v = fmaxf(v, 0.f);
                    C[(size_t)gm * ldc + gn] = v;
                }
            }
        }
    }
#undef FETCH
#undef COMMIT
}

// ---------------------------------------------------------------------------
// Attention prop0: per node, 2 heads, 10x10, hd=136
// ---------------------------------------------------------------------------
__global__ void __launch_bounds__(256)
attn0_kernel(const float* __restrict__ qp, const float* __restrict__ kvp,
             float* __restrict__ o)
{
    __shared__ float Qs[NB][EQ];
    __shared__ float Ks[NB][EQ];
    __shared__ float Vs[NB][EQ];
    __shared__ float P[2][NB][NB];

    const int s = blockIdx.x;
    const int tid = threadIdx.x;
    const size_t base = (size_t)s * NB;

    for (int i = tid; i < NB * EQ; i += 256) {
        int r = i / EQ, f = i - r * EQ;
        Qs[r][f] = qp[(base + r) * EQ + f];
        Ks[r][f] = kvp[(base + r) * 544 + f];
        Vs[r][f] = kvp[(base + r) * 544 + EQ + f];
    }
    __syncthreads();

    if (tid < 200) {
        int h = tid / 100, rem = tid - h * 100;
        int qi = rem / NB, ki = rem - qi * NB;
        const float* q = &Qs[qi][h * HD];
        const float* k = &Ks[ki][h * HD];
        float acc = 0.f;
#pragma unroll 8
        for (int d = 0; d < HD; d++) acc = fmaf(q[d], k[d], acc);
        P[h][qi][ki] = acc;
    }
    __syncthreads();

    if (tid < 20) {
        int h = tid / NB, qi = tid - h * NB;
        float mx = -1e30f;
#pragma unroll
        for (int ki = 0; ki < NB; ki++) mx = fmaxf(mx, P[h][qi][ki]);
        float sum = 0.f;
#pragma unroll
        for (int ki = 0; ki < NB; ki++) {
            float e = expf(P[h][qi][ki] - mx);
            P[h][qi][ki] = e;
            sum += e;
        }
        float inv = 1.f / sum;
#pragma unroll
        for (int ki = 0; ki < NB; ki++) P[h][qi][ki] *= inv;
    }
    __syncthreads();

    for (int i = tid; i < NB * EQ; i += 256) {
        int qi = i / EQ, f = i - qi * EQ;
        int h = f / HD;
        float acc = 0.f;
#pragma unroll
        for (int ki = 0; ki < NB; ki++) acc = fmaf(P[h][qi][ki], Vs[ki][f], acc);
        o[(base + qi) * EQ + f] = acc;
    }
}

// ---------------------------------------------------------------------------
// Attention prop1: full 2048x2048, flash-style online softmax
// ---------------------------------------------------------------------------
#define A1_BQ   32
#define A1_BK   64
#define A1_KP   137
#define A1_PP   65
#define A1_SMEM_FLOATS (A1_BQ*HD + 2*A1_BK*A1_KP + A1_BQ*A1_PP + 3*A1_BQ)

__global__ void __launch_bounds__(256)
attn1_kernel(const float* __restrict__ qp, const float* __restrict__ kvp,
             float* __restrict__ o)
{
    extern __shared__ float sm[];
    float* Qs = sm;
    float* Ksm = Qs + A1_BQ * HD;
    float* Vsm = Ksm + A1_BK * A1_KP;
    float* Ps  = Vsm + A1_BK * A1_KP;
    float* m_s = Ps + A1_BQ * A1_PP;
    float* l_s = m_s + A1_BQ;
    float* al_s = l_s + A1_BQ;

    const int h  = blockIdx.y;
    const int q0 = blockIdx.x * A1_BQ;
    const int tid = threadIdx.x;

    for (int i = tid; i < A1_BQ * HD; i += 256) {
        int r = i / HD, d = i - r * HD;
        Qs[r * HD + d] = qp[(size_t)(q0 + r) * EQ + h * HD + d];
    }
    if (tid < A1_BQ) { m_s[tid] = -1e30f; l_s[tid] = 0.f; }

    const int qown = tid >> 3;
    const int dg   = tid & 7;
    const int tyq  = tid >> 5;
    const int txk  = tid & 31;

    float oacc[17];
#pragma unroll
    for (int j = 0; j < 17; j++) oacc[j] = 0.f;

    for (int kt = 0; kt < SRC; kt += A1_BK) {
        __syncthreads();
        for (int i = tid; i < A1_BK * HD; i += 256) {
            int r = i / HD, d = i - r * HD;
            Ksm[r * A1_KP + d] = kvp[(size_t)(kt + r) * 544 + h * HD + d];
            Vsm[r * A1_KP + d] = kvp[(size_t)(kt + r) * 544 + EQ + h * HD + d];
        }
        __syncthreads();

        float sc[4][2];
#pragma unroll
        for (int i = 0; i < 4; i++) { sc[i][0] = 0.f; sc[i][1] = 0.f; }
        const float* krow0 = &Ksm[(txk * 2 + 0) * A1_KP];
        const float* krow1 = &Ksm[(txk * 2 + 1) * A1_KP];
#pragma unroll 4
        for (int d = 0; d < HD; d++) {
            float kv0 = krow0[d];
            float kv1 = krow1[d];
#pragma unroll
            for (int i = 0; i < 4; i++) {
                float qv = Qs[(tyq * 4 + i) * HD + d];
                sc[i][0] = fmaf(qv, kv0, sc[i][0]);
                sc[i][1] = fmaf(qv, kv1, sc[i][1]);
            }
        }
#pragma unroll
        for (int i = 0; i < 4; i++) {
            Ps[(tyq * 4 + i) * A1_PP + txk * 2 + 0] = sc[i][0];
            Ps[(tyq * 4 + i) * A1_PP + txk * 2 + 1] = sc[i][1];
        }
        __syncthreads();

        if (tid < A1_BQ) {
            float mx = m_s[tid];
            float* prow = &Ps[tid * A1_PP];
#pragma unroll 8
            for (int j = 0; j < A1_BK; j++) mx = fmaxf(mx, prow[j]);
            float al = expf(m_s[tid] - mx);
            float sum = 0.f;
#pragma unroll 8
            for (int j = 0; j < A1_BK; j++) {
                float e = expf(prow[j] - mx);
                prow[j] = e;
                sum += e;
            }
            l_s[tid] = l_s[tid] * al + sum;
            m_s[tid] = mx;
            al_s[tid] = al;
        }
        __syncthreads();

        float al = al_s[qown];
#pragma unroll
        for (int j = 0; j < 17; j++) oacc[j] *= al;
        const float* prow = &Ps[qown * A1_PP];
#pragma unroll 2
        for (int ki = 0; ki < A1_BK; ki++) {
            float p = prow[ki];
            const float* vrow = &Vsm[ki * A1_KP + dg * 17];
#pragma unroll
            for (int j = 0; j < 17; j++) oacc[j] = fmaf(p, vrow[j], oacc[j]);
        }
    }

    float inv = 1.f / l_s[qown];
#pragma unroll
    for (int j = 0; j < 17; j++)
        o[(size_t)(q0 + qown) * EQ + h * HD + dg * 17 + j] = oacc[j] * inv;
}

// ---------------------------------------------------------------------------
// Host launch
// ---------------------------------------------------------------------------
extern "C" void kernel_launch(void* const* d_in, const int* in_sizes, int n_in,
                              void* d_out, int out_size)
{
    const float* emb0  = (const float*)d_in[0];
    const float* edge0 = (const float*)d_in[1];
    const float* td0   = (const float*)d_in[2];
    const float* emb1  = (const float*)d_in[3];
    const float* edge1 = (const float*)d_in[4];
    const float* td1   = (const float*)d_in[5];
    const float* emb2  = (const float*)d_in[6];
    const float* Wq    = (const float*)d_in[7];
    const float* bq    = (const float*)d_in[8];
    const float* Wk    = (const float*)d_in[9];
    const float* bk    = (const float*)d_in[10];
    const float* Wv    = (const float*)d_in[11];
    const float* bv    = (const float*)d_in[12];
    const float* Wo    = (const float*)d_in[13];
    const float* bo    = (const float*)d_in[14];
    const float* W1    = (const float*)d_in[15];
    const float* b1    = (const float*)d_in[16];
    const float* W2    = (const float*)d_in[17];
    const float* b2    = (const float*)d_in[18];
    float* out = (float*)d_out;

    float *kvp0, *qp0, *o0, *a0, *h0, *kvp1, *qp1, *o1, *a1, *h1;
    cudaGetSymbolAddress((void**)&kvp0, g_kvp0);
    cudaGetSymbolAddress((void**)&qp0,  g_qp0);
    cudaGetSymbolAddress((void**)&o0,   g_o0);
    cudaGetSymbolAddress((void**)&a0,   g_a0);
    cudaGetSymbolAddress((void**)&h0,   g_h0);
    cudaGetSymbolAddress((void**)&kvp1, g_kvp1);
    cudaGetSymbolAddress((void**)&qp1,  g_qp1);
    cudaGetSymbolAddress((void**)&o1,   g_o1);
    cudaGetSymbolAddress((void**)&a1,   g_a1);
    cudaGetSymbolAddress((void**)&h1,   g_h1);

    const float scale = 1.0f / sqrtf((float)HD);
    const int smem1 = A1_SMEM_FLOATS * (int)sizeof(float);
    cudaFuncSetAttribute(attn1_kernel,
                         cudaFuncAttributeMaxDynamicSharedMemorySize, smem1);
    cudaFuncSetAttribute(gemm_mma<1, 1, false>,
                         cudaFuncAttributeMaxDynamicSharedMemorySize, GM_SMEM);
    cudaFuncSetAttribute(gemm_mma<2, 0, false>,
                         cudaFuncAttributeMaxDynamicSharedMemorySize, GM_SMEM);
    cudaFuncSetAttribute(gemm_mma<0, 0, false>,
                         cudaFuncAttributeMaxDynamicSharedMemorySize, GM_SMEM);
    cudaFuncSetAttribute(gemm_mma<3, 0, true>,
                         cudaFuncAttributeMaxDynamicSharedMemorySize, GM_SMEM);

    // ---------------- propagation 0 ----------------
    // fused K/V projection: (20480 x 4440) x (4440 x 544)
    gemm_mma<1, 1, false><<<dim3(9, 160), 256, GM_SMEM>>>(
        emb0, edge0, td0, 0, Wk, Wv, KDT, bk, bv,
        kvp0, M0, 544, KDT, 544, 1.f);
    // Q projection
    gemm_mma<2, 0, false><<<dim3(5, 160), 256, GM_SMEM>>>(
        emb1, td1, nullptr, 0, Wq, nullptr, EQ, bq, nullptr,
        qp0, M0, EQ, EQ, EQ, scale);
    attn0_kernel<<<SRC, 256>>>(qp0, kvp0, o0);
    // output projection
    gemm_mma<0, 0, false><<<dim3(5, 160), 256, GM_SMEM>>>(
        o0, nullptr, nullptr, EQ, Wo, nullptr, EQ, bo, nullptr,
        a0, M0, EQ, EQ, EQ, 1.f);
    // FFN
    gemm_mma<3, 0, true><<<dim3(3, 160), 256, GM_SMEM>>>(
        a0, emb1, nullptr, 0, W1, nullptr, EQ + DDIM, b1, nullptr,
        h0, M0, DDIM, EQ + DDIM, DDIM, 1.f);
    gemm_mma<0, 0, false><<<dim3(3, 160), 256, GM_SMEM>>>(
        h0, nullptr, nullptr, DDIM, W2, nullptr, DDIM, b2, nullptr,
        out + OUT_R0, M0, DDIM, DDIM, DDIM, 1.f);

    // ---------------- propagation 1 ----------------
    gemm_mma<1, 1, false><<<dim3(9, 16), 256, GM_SMEM>>>(
        emb1, edge1, td1, 0, Wk, Wv, KDT, bk, bv,
        kvp1, M1, 544, KDT, 544, 1.f);
    // Q projection: q = [emb2, zeros(100)] -> only first 172 cols of Wq matter
    gemm_mma<0, 0, false><<<dim3(5, 16), 256, GM_SMEM>>>(
        emb2, nullptr, nullptr, DDIM, Wq, nullptr, EQ, bq, nullptr,
        qp1, M1, EQ, DDIM, EQ, scale);
    attn1_kernel<<<dim3(SRC / A1_BQ, 2), 256, smem1>>>(qp1, kvp1, o1);
    gemm_mma<0, 0, false><<<dim3(5, 16), 256, GM_SMEM>>>(
        o1, nullptr, nullptr, EQ, Wo, nullptr, EQ, bo, nullptr,
        a1, M1, EQ, EQ, EQ, 1.f);
    gemm_mma<3, 0, true><<<dim3(3, 16), 256, GM_SMEM>>>(
        a1, emb2, nullptr, 0, W1, nullptr, EQ + DDIM, b1, nullptr,
        h1, M1, DDIM, EQ + DDIM, DDIM, 1.f);
    gemm_mma<0, 0, false><<<dim3(3, 16), 256, GM_SMEM>>>(
        h1, nullptr, nullptr, DDIM, W2, nullptr, DDIM, b2, nullptr,
        out + OUT_R1, M1, DDIM, DDIM, DDIM, 1.f);

    // ---------------- passthrough outputs ----------------
    cudaMemcpyAsync(out + OUT_EDGE, edge1, (size_t)SRC * NB * EDIM * sizeof(float),
                    cudaMemcpyDeviceToDevice);
    cudaMemcpyAsync(out + OUT_TD, td1, (size_t)SRC * NB * TDIM * sizeof(float),
                    cudaMemcpyDeviceToDevice);
}